// round 9
// baseline (speedup 1.0000x reference)
#include <cuda_runtime.h>
#include <cuda_fp16.h>
#include <math.h>

#define BC        1024       // 8 * 128 merged batch*channel
#define LIN       65536
#define LOUT      16384
#define KNB       9
#define CHUNK_BC  256        // bc per pipeline chunk
#define NCHUNK    (BC / CHUNK_BC)          // 4
#define CHUNK_EL  ((size_t)LIN * CHUNK_BC) // halves per chunk buffer (32 MB)

// 64 MB ping-pong scratch, L2-resident: buf[p][i][bcp], bcp < 256
__device__ __half g_buf[2 * CHUNK_EL];

// ---------------------------------------------------------------------------
// Combined kernel: gather of chunk gc (reads buf[gc&1]) runs concurrently
// with transpose of chunk tc (writes buf[tc&1]). Either may be -1 (skipped).
// In mixed launches the roles are INTERLEAVED across blockIdx (every 9th CTA
// is a gather CTA) so every wave carries both DRAM-streaming transpose work
// and latency-bound gather work.
// ---------------------------------------------------------------------------
__global__ __launch_bounds__(256, 6) void pool_kernel(const float* __restrict__ x,
                                                      const int*   __restrict__ nb,
                                                      float*       __restrict__ out,
                                                      int gc, int tc) {
    __shared__ __align__(16) char sm_raw[16896];   // union: gather 16.9KB / transpose 16.6KB

    const int t    = threadIdx.x;
    const int w    = t >> 5;
    const int lane = t & 31;

    // role assignment
    bool isGather;
    int gidx = 0, tidx = 0;
    if (gc >= 0 && tc >= 0) {
        int a = blockIdx.x / 9;
        int r = blockIdx.x - 9 * a;
        isGather = (r == 0);
        gidx = a;
        tidx = 8 * a + r - 1;
    } else if (gc >= 0) {
        isGather = true;  gidx = blockIdx.x;
    } else {
        isGather = false; tidx = blockIdx.x;
    }

    if (isGather) {
        // ================= GATHER: chunk gc =================
        // CTA = (l tile of 128) x (64-bc sub-slice). lane gathers half2 ->
        // warp load = 128B fully-used. 9 loads batched per l, tree-reduce.
        __half* s_out = (__half*)sm_raw;               // [128][66]

        const int lTile = gidx >> 2;
        const int sub   = gidx & 3;
        const int lBase = lTile * 128;

        int myIdx[KNB];
        const int myL = lBase + w * 16 + (lane & 15);  // lanes 16-31 mirror
        #pragma unroll
        for (int k = 0; k < KNB; k++)
            myIdx[k] = __ldg(nb + (size_t)k * LOUT + myL);

        const __half2* xb = (const __half2*)(g_buf + (size_t)(gc & 1) * CHUNK_EL)
                            + sub * 32 + lane;

        #pragma unroll 1
        for (int m = 0; m < 16; m += 4) {
            __half2 acc[4];
            #pragma unroll
            for (int j = 0; j < 4; j++) {
                __half2 v[KNB];
                #pragma unroll
                for (int k = 0; k < KNB; k++) {
                    int i = __shfl_sync(0xffffffffu, myIdx[k], m + j);
                    v[k] = __ldg(xb + (size_t)i * 128);   // row stride 256 halves
                }
                __half2 m01 = __hmax2(v[0], v[1]);
                __half2 m23 = __hmax2(v[2], v[3]);
                __half2 m45 = __hmax2(v[4], v[5]);
                __half2 m67 = __hmax2(v[6], v[7]);
                m01 = __hmax2(m01, m23);
                m45 = __hmax2(m45, m67);
                acc[j] = __hmax2(__hmax2(m01, m45), v[8]);
            }
            const int ll = w * 16 + m;
            __half2* so = (__half2*)s_out;
            #pragma unroll
            for (int j = 0; j < 4; j++)
                so[(ll + j) * 33 + lane] = acc[j];   // bank (ll+j+lane)%32: free
        }
        __syncthreads();

        // writeback: t -> l = t&127, bc group (t>>7)*32; 128B coalesced stores
        const int l = t & 127;
        const int g = (t >> 7) * 32;
        float* ob = out + (size_t)(gc * CHUNK_BC + sub * 64 + g) * LOUT + lBase + l;
        #pragma unroll
        for (int b = 0; b < 32; b++)
            __stcs(ob + (size_t)b * LOUT, __half2float(s_out[l * 66 + g + b]));

    } else {
        // ================= TRANSPOSE: chunk tc =================
        // Tile: 64 bc x 64 i. Scalar STS (row stride 65 floats: not 16B-aligned).
        float (*tile)[65] = (float (*)[65])sm_raw;

        const int iBase  = (tidx >> 2) * 64;
        const int bcT    = tidx & 3;
        const int bcBase = tc * CHUNK_BC + bcT * 64;

        const int r = t >> 2;    // bc row 0..63
        const int q = t & 3;     // 0..3
        const float4* x4 = (const float4*)(x + (size_t)(bcBase + r) * LIN + iBase);
        #pragma unroll
        for (int m = 0; m < 4; m++) {
            float4 v = __ldcs(x4 + q + 4 * m);   // streaming: don't evict scratch
            int c = (q + 4 * m) * 4;
            tile[r][c + 0] = v.x;
            tile[r][c + 1] = v.y;
            tile[r][c + 2] = v.z;
            tile[r][c + 3] = v.w;
        }
        __syncthreads();

        // store: warp w owns i = w*8..w*8+7; per i warp writes 128B contiguous
        __half2* dst = (__half2*)(g_buf + (size_t)(tc & 1) * CHUNK_EL)
                       + bcT * 32 + lane;
        #pragma unroll
        for (int s = 0; s < 8; s++) {
            int i = w * 8 + s;
            // tile[2lane][i]: bank (2lane+i)%32 -> 2-way max
            __half2 v = __floats2half2_rn(tile[2 * lane][i], tile[2 * lane + 1][i]);
            dst[(size_t)(iBase + i) * 128] = v;
        }
    }
}

// ---------------------------------------------------------------------------
extern "C" void kernel_launch(void* const* d_in, const int* in_sizes, int n_in,
                              void* d_out, int out_size) {
    const float* x   = (const float*)d_in[0];
    const int*   nb  = (const int*)d_in[1];
    float*       out = (float*)d_out;

    (void)in_sizes; (void)n_in; (void)out_size;

    const int TGRID = (LIN / 64) * (CHUNK_BC / 64);   // 4096
    const int GGRID = (LOUT / 128) * 4;               // 512

    pool_kernel<<<TGRID, 256>>>(x, nb, out, -1, 0);           // T0
    pool_kernel<<<GGRID + TGRID, 256>>>(x, nb, out, 0, 1);    // G0 || T1 (interleaved)
    pool_kernel<<<GGRID + TGRID, 256>>>(x, nb, out, 1, 2);    // G1 || T2
    pool_kernel<<<GGRID + TGRID, 256>>>(x, nb, out, 2, 3);    // G2 || T3
    pool_kernel<<<GGRID, 256>>>(x, nb, out, 3, -1);           // G3
}

// round 10
// speedup vs baseline: 1.1277x; 1.1277x over previous
#include <cuda_runtime.h>
#include <cuda_fp16.h>
#include <math.h>

#define BC        1024       // 8 * 128 merged batch*channel
#define LIN       65536
#define LOUT      16384
#define KNB       9
#define CHUNK_BC  256        // bc per pipeline chunk
#define NCHUNK    (BC / CHUNK_BC)          // 4
#define CHUNK_EL  ((size_t)LIN * CHUNK_BC) // halves per chunk buffer (32 MB)

#define GLT       64         // l per gather CTA
#define GSUB      4          // 64-bc sub-slices per chunk
#define GGRID     ((LOUT / GLT) * GSUB)    // 1024 gather CTAs per chunk

// 64 MB ping-pong scratch, L2-resident: buf[p][i][bcp], bcp < 256
__device__ __half g_buf[2 * CHUNK_EL];

// ---------------------------------------------------------------------------
// Combined kernel: gather of chunk gc (reads buf[gc&1]) + transpose of chunk
// tc (writes buf[tc&1]) in one launch. Gather CTAs take the LOW blockIdx
// range (first wave; warm L2), transposes fill the remaining waves.
// ---------------------------------------------------------------------------
__global__ __launch_bounds__(256) void pool_kernel(const float* __restrict__ x,
                                                   const int*   __restrict__ nb,
                                                   float*       __restrict__ out,
                                                   int gc, int tc) {
    __shared__ __align__(16) char sm_raw[16640];   // union: transpose 16.6KB / gather 8.4KB

    const int t    = threadIdx.x;
    const int w    = t >> 5;
    const int lane = t & 31;
    const int gN   = (gc >= 0) ? GGRID : 0;

    if ((int)blockIdx.x < gN) {
        // ================= GATHER: chunk gc =================
        // CTA = (l tile of 64) x (64-bc sub-slice). lane gathers half2 ->
        // warp load = 128B fully-used. 9 loads batched per l, tree-reduce.
        __half* s_out = (__half*)sm_raw;               // [64][66] = 8.4 KB

        const int gidx  = blockIdx.x;
        const int lTile = gidx >> 2;
        const int sub   = gidx & 3;
        const int lBase = lTile * GLT;

        // warp owns 8 l's; lanes 0-7 hold index columns (others mirror)
        int myIdx[KNB];
        const int myL = lBase + w * 8 + (lane & 7);
        #pragma unroll
        for (int k = 0; k < KNB; k++)
            myIdx[k] = __ldg(nb + (size_t)k * LOUT + myL);

        const __half2* xb = (const __half2*)(g_buf + (size_t)(gc & 1) * CHUNK_EL)
                            + sub * 32 + lane;

        #pragma unroll 1
        for (int m = 0; m < 8; m += 4) {
            __half2 acc[4];
            #pragma unroll
            for (int j = 0; j < 4; j++) {
                __half2 v[KNB];
                #pragma unroll
                for (int k = 0; k < KNB; k++) {
                    int i = __shfl_sync(0xffffffffu, myIdx[k], m + j);
                    v[k] = __ldg(xb + (size_t)i * 128);   // row stride 256 halves
                }
                __half2 m01 = __hmax2(v[0], v[1]);
                __half2 m23 = __hmax2(v[2], v[3]);
                __half2 m45 = __hmax2(v[4], v[5]);
                __half2 m67 = __hmax2(v[6], v[7]);
                m01 = __hmax2(m01, m23);
                m45 = __hmax2(m45, m67);
                acc[j] = __hmax2(__hmax2(m01, m45), v[8]);
            }
            const int ll = w * 8 + m;
            __half2* so = (__half2*)s_out;
            #pragma unroll
            for (int j = 0; j < 4; j++)
                so[(ll + j) * 33 + lane] = acc[j];   // bank (ll+j+lane)%32: free
        }
        __syncthreads();

        // writeback: t -> l = t&63, bc group (t>>6)*16; 128B coalesced stores
        const int l = t & 63;
        const int g = (t >> 6) * 16;
        float* ob = out + (size_t)(gc * CHUNK_BC + sub * 64 + g) * LOUT + lBase + l;
        #pragma unroll
        for (int b = 0; b < 16; b++)
            __stcs(ob + (size_t)b * LOUT, __half2float(s_out[l * 66 + g + b]));

    } else if (tc >= 0) {
        // ================= TRANSPOSE: chunk tc =================
        // Tile: 64 bc x 64 i. Scalar STS (row stride 65 floats: not 16B-aligned).
        float (*tile)[65] = (float (*)[65])sm_raw;

        const int tidx   = blockIdx.x - gN;
        const int iBase  = (tidx >> 2) * 64;
        const int bcT    = tidx & 3;
        const int bcBase = tc * CHUNK_BC + bcT * 64;

        const int r = t >> 2;    // bc row 0..63
        const int q = t & 3;     // 0..3
        const float4* x4 = (const float4*)(x + (size_t)(bcBase + r) * LIN + iBase);
        #pragma unroll
        for (int m = 0; m < 4; m++) {
            float4 v = __ldcs(x4 + q + 4 * m);   // streaming: don't evict scratch
            int c = (q + 4 * m) * 4;
            tile[r][c + 0] = v.x;
            tile[r][c + 1] = v.y;
            tile[r][c + 2] = v.z;
            tile[r][c + 3] = v.w;
        }
        __syncthreads();

        // store: warp w owns i = w*8..w*8+7; per i warp writes 128B contiguous
        __half2* dst = (__half2*)(g_buf + (size_t)(tc & 1) * CHUNK_EL)
                       + bcT * 32 + lane;
        #pragma unroll
        for (int s = 0; s < 8; s++) {
            int i = w * 8 + s;
            // tile[2lane][i]: bank (2lane+i)%32 -> 2-way max
            __half2 v = __floats2half2_rn(tile[2 * lane][i], tile[2 * lane + 1][i]);
            dst[(size_t)(iBase + i) * 128] = v;
        }
    }
}

// ---------------------------------------------------------------------------
extern "C" void kernel_launch(void* const* d_in, const int* in_sizes, int n_in,
                              void* d_out, int out_size) {
    const float* x   = (const float*)d_in[0];
    const int*   nb  = (const int*)d_in[1];
    float*       out = (float*)d_out;

    (void)in_sizes; (void)n_in; (void)out_size;

    const int TGRID = (LIN / 64) * (CHUNK_BC / 64);   // 4096

    pool_kernel<<<TGRID, 256>>>(x, nb, out, -1, 0);           // T0
    pool_kernel<<<GGRID + TGRID, 256>>>(x, nb, out, 0, 1);    // G0 || T1
    pool_kernel<<<GGRID + TGRID, 256>>>(x, nb, out, 1, 2);    // G1 || T2
    pool_kernel<<<GGRID + TGRID, 256>>>(x, nb, out, 2, 3);    // G2 || T3
    pool_kernel<<<GGRID, 256>>>(x, nb, out, 3, -1);           // G3
}